// round 7
// baseline (speedup 1.0000x reference)
#include <cuda_runtime.h>

// SplitWin_Normalize R7: R6 with float2 lanes instead of float4.
// Same TB=32, same window-init positions -> bitwise-identical per-element
// arithmetic to R6 (rel_err unchanged). Doubles total warps (4096 -> 8192,
// ~55/SM) to hide L2-hit latency on the window taps, which R6's profile
// showed as the binding constraint (occ 46%, issue 31%, nothing saturated).
// Layout: (4096 bins [stride NL], 4096 lines [contiguous]).

static const int NB = 4096;
static const int NL = 4096;
static const int TB = 32;            // bins per thread in stream tiles
static const int NTY = NB / TB;      // 128 stream tiles
static const int THREADS = 256;
static const int L2N = NL / 2;       // float2 lanes per row (2048)

__device__ float g_c1[NB * NL];
__device__ float g_c2[NB * NL];

__device__ __forceinline__ int refl(int p)
{
    if (p < 0)   return -1 - p;
    if (p >= NB) return 2 * NB - 1 - p;
    return p;
}

__device__ __forceinline__ float2 ld2(const float* __restrict__ p, int row, int l2)
{
    return __ldg(reinterpret_cast<const float2*>(p) + row * L2N + l2);
}

__device__ __forceinline__ float2 f2add(float2 a, float2 b)
{ return make_float2(a.x + b.x, a.y + b.y); }
__device__ __forceinline__ float2 f2sub(float2 a, float2 b)
{ return make_float2(a.x - b.x, a.y - b.y); }
__device__ __forceinline__ float2 f2scale(float2 a, float s)
{ return make_float2(a.x * s, a.y * s); }
__device__ __forceinline__ float2 f2clip(float2 xv, float2 sm, float clip)
{
    return make_float2((xv.x > clip * sm.x) ? sm.x : xv.x,
                       (xv.y > clip * sm.y) ? sm.y : xv.y);
}

// ---------------------------------------------------------------------------
// Stage kernel (w=41, gap=20): grid = (L2N/THREADS, NTY + 83).
//  y <  NTY : streaming interior tile (fast path when no reflect possible)
//  y >= NTY : one edge bin, brute-forced.
// ---------------------------------------------------------------------------
__global__ void stage_kernel(const float* __restrict__ src,
                             float* __restrict__ dst, float clip)
{
    const int l2 = blockIdx.x * THREADS + threadIdx.x;
    const float SC = 0.5f / 41.0f;
    float2* __restrict__ dst2 = reinterpret_cast<float2*>(dst);

    if (blockIdx.y >= NTY) {
        int j = blockIdx.y - NTY;                    // 0..82
        int i = (j < 42) ? j : (NB - 41 + (j - 42));
        int f = (i + 41 < NB) ? (i + 41) : (2 * NB - 43 - i);
        int a = (i <= 41) ? (41 - i) : (i - 42);
        float2 sf = make_float2(0.f, 0.f);
        float2 sa = make_float2(0.f, 0.f);
        #pragma unroll 4
        for (int k = -20; k <= 20; ++k) {
            sf = f2add(sf, ld2(src, refl(f + k), l2));
            sa = f2add(sa, ld2(src, refl(a + k), l2));
        }
        float2 sm = f2scale(f2add(sf, sa), SC);
        float2 xv = ld2(src, i, l2);
        dst2[i * L2N + l2] = f2clip(xv, sm, clip);
        return;
    }

    const int t0 = blockIdx.y * TB;
    int i0 = (t0 < 42) ? 42 : t0;
    int i1 = t0 + TB - 1;
    if (i1 > NB - 42) i1 = NB - 42;
    if (i0 > i1) return;

    float2 Wf = make_float2(0.f, 0.f);
    float2 Wa = make_float2(0.f, 0.f);

    const bool fast = (t0 >= 62) && (t0 + TB - 1 + 62 <= NB - 1);

    if (fast) {
        #pragma unroll 4
        for (int k = 21; k <= 61; ++k) Wf = f2add(Wf, ld2(src, i0 + k, l2));
        #pragma unroll 4
        for (int k = 22; k <= 62; ++k) Wa = f2add(Wa, ld2(src, i0 - k, l2));

        #pragma unroll 8
        for (int i = i0; i <= i1; ++i) {
            float2 sm = f2scale(f2add(Wf, Wa), SC);
            float2 xv = ld2(src, i, l2);
            dst2[i * L2N + l2] = f2clip(xv, sm, clip);
            float2 nf = ld2(src, i + 62, l2);
            float2 of = ld2(src, i + 21, l2);
            float2 na = ld2(src, i - 21, l2);
            float2 oa = ld2(src, i - 62, l2);
            Wf = f2add(Wf, f2sub(nf, of));
            Wa = f2add(Wa, f2sub(na, oa));
        }
    } else {
        #pragma unroll 4
        for (int k = 21; k <= 61; ++k) Wf = f2add(Wf, ld2(src, refl(i0 + k), l2));
        #pragma unroll 4
        for (int k = 22; k <= 62; ++k) Wa = f2add(Wa, ld2(src, refl(i0 - k), l2));

        #pragma unroll 4
        for (int i = i0; i <= i1; ++i) {
            float2 sm = f2scale(f2add(Wf, Wa), SC);
            float2 xv = ld2(src, i, l2);
            dst2[i * L2N + l2] = f2clip(xv, sm, clip);
            float2 nf = ld2(src, refl(i + 62), l2);
            float2 of = ld2(src, refl(i + 21), l2);
            float2 na = ld2(src, refl(i - 21), l2);
            float2 oa = ld2(src, refl(i - 62), l2);
            Wf = f2add(Wf, f2sub(nf, of));
            Wa = f2add(Wa, f2sub(na, oa));
        }
    }
}

// ---------------------------------------------------------------------------
// Stage 3 (w=25, gap=0) + final divide: out = x / box25(c2).
// grid = (L2N/THREADS, NTY). Fast path for tiles needing no reflection.
// ---------------------------------------------------------------------------
__global__ void stage3_kernel(const float* __restrict__ c2,
                              const float* __restrict__ x,
                              float* __restrict__ out)
{
    const int l2 = blockIdx.x * THREADS + threadIdx.x;
    const int t0 = blockIdx.y * TB;
    const int i1 = t0 + TB - 1;
    const float R25 = 1.0f / 25.0f;
    float2* __restrict__ out2 = reinterpret_cast<float2*>(out);

    float2 W = make_float2(0.f, 0.f);
    const bool fast = (t0 >= 13) && (i1 + 13 <= NB - 1);

    if (fast) {
        #pragma unroll
        for (int k = -12; k <= 12; ++k) W = f2add(W, ld2(c2, t0 + k, l2));

        #pragma unroll 8
        for (int i = t0; i <= i1; ++i) {
            float2 f  = f2scale(W, R25);
            float2 xv = ld2(x, i, l2);
            out2[i * L2N + l2] = make_float2(__fdiv_rn(xv.x, f.x),
                                             __fdiv_rn(xv.y, f.y));
            W = f2add(W, f2sub(ld2(c2, i + 13, l2), ld2(c2, i - 12, l2)));
        }
    } else {
        #pragma unroll
        for (int k = -12; k <= 12; ++k) W = f2add(W, ld2(c2, refl(t0 + k), l2));

        #pragma unroll 4
        for (int i = t0; i <= i1; ++i) {
            float2 f  = f2scale(W, R25);
            float2 xv = ld2(x, i, l2);
            out2[i * L2N + l2] = make_float2(__fdiv_rn(xv.x, f.x),
                                             __fdiv_rn(xv.y, f.y));
            W = f2add(W, f2sub(ld2(c2, refl(i + 13), l2),
                               ld2(c2, refl(i - 12), l2)));
        }
    }
}

// ---------------------------------------------------------------------------
extern "C" void kernel_launch(void* const* d_in, const int* in_sizes, int n_in,
                              void* d_out, int out_size)
{
    const float* x = (const float*)d_in[0];
    float* out     = (float*)d_out;

    float *c1 = nullptr, *c2 = nullptr;
    cudaGetSymbolAddress((void**)&c1, g_c1);
    cudaGetSymbolAddress((void**)&c2, g_c2);

    dim3 blk(THREADS);
    dim3 gStage(L2N / THREADS, NTY + 83);   // (8, 211)
    dim3 gS3(L2N / THREADS, NTY);           // (8, 128)

    stage_kernel<<<gStage, blk>>>(x,  c1, 3.0f);
    stage_kernel<<<gStage, blk>>>(c1, c2, 2.0f);
    stage3_kernel<<<gS3, blk>>>(c2, x, out);
}